// round 1
// baseline (speedup 1.0000x reference)
#include <cuda_runtime.h>

#define BB 8
#define SS 2048
#define HH 768
#define DD 32
#define NP (BB*SS)   // 16384 total rows

// ---------------- scratch (no cudaMalloc allowed) ----------------
__device__ float g_Wcat[HH*96];   // [h][0:32)=Wqr*invsqrtD, [32:64)=Wkr, [64:96)=Wv^T
__device__ float g_bcat[96];
__device__ float g_qr[NP*DD];
__device__ float g_kr[NP*DD];
__device__ float g_v [NP*DD];
__device__ float g_invsum[NP];

// ---------------- fast exp on the FMA pipe (avoid MUFU bottleneck) ----------------
__device__ __forceinline__ float fexp(float x) {
    float y = x * 1.4426950408889634f;   // x * log2(e)
    float n = rintf(y);
    float f = y - n;                     // f in [-0.5, 0.5]
    // 2^f Taylor, degree 5: abs err ~2.4e-6
    float p = 1.3333558146e-3f;
    p = fmaf(p, f, 9.6181291976e-3f);
    p = fmaf(p, f, 5.5504108664e-2f);
    p = fmaf(p, f, 2.4022650695910071e-1f);
    p = fmaf(p, f, 6.9314718055994531e-1f);
    p = fmaf(p, f, 1.0f);
    int ni = (int)n;
    return __int_as_float(__float_as_int(p) + (ni << 23));
}

// ---------------- kernel 0: fold RF (and 1/sqrt(D)) into projection weights ----------------
__global__ void prep_kernel(const float* __restrict__ Wq, const float* __restrict__ bq,
                            const float* __restrict__ Wk, const float* __restrict__ bk,
                            const float* __restrict__ Wv, const float* __restrict__ bv,
                            const float* __restrict__ RF) {
    int idx = blockIdx.x * blockDim.x + threadIdx.x;
    const float invsD = 0.17677669529663687f;  // 1/sqrt(32)
    if (idx < HH*96) {
        int h = idx / 96, j = idx % 96;
        float r;
        if (j < 64) {
            const float* W = (j < 32) ? Wq : Wk;
            int f = j & 31;
            float acc = 0.f;
            #pragma unroll
            for (int d = 0; d < 32; d++) acc = fmaf(W[d*HH + h], RF[d*32 + f], acc);
            r = (j < 32) ? acc * invsD : acc;
        } else {
            r = Wv[(j - 64)*HH + h];
        }
        g_Wcat[h*96 + j] = r;
    } else if (idx < HH*96 + 96) {
        int j = idx - HH*96;
        float r;
        if (j < 64) {
            const float* bb = (j < 32) ? bq : bk;
            int f = j & 31;
            float acc = 0.f;
            #pragma unroll
            for (int d = 0; d < 32; d++) acc = fmaf(bb[d], RF[d*32 + f], acc);
            r = (j < 32) ? acc * invsD : acc;
        } else {
            r = bv[j - 64];
        }
        g_bcat[j] = r;
    }
}

// ---------------- kernel 1: fused projection GEMM  [16384,768] @ [768,96] ----------------
__global__ __launch_bounds__(256) void proj_kernel(const float* __restrict__ x) {
    __shared__ float xs[64][32];
    __shared__ float ws[32][96];
    __shared__ float bs[96];
    int tid = threadIdx.x;
    int n0 = blockIdx.x * 64;
    if (tid < 96) bs[tid] = g_bcat[tid];
    int tr = tid >> 4, tc = tid & 15;   // 16x16 threads; each does 4 rows x 6 cols
    __syncthreads();

    float acc[4][6];
    #pragma unroll
    for (int i = 0; i < 4; i++)
        #pragma unroll
        for (int j = 0; j < 6; j++) acc[i][j] = bs[tc*6 + j];

    for (int kk = 0; kk < HH; kk += 32) {
        #pragma unroll
        for (int l = 0; l < 2; l++) {
            int slot = tid*2 + l;
            int r = slot >> 3, kq = (slot & 7) << 2;
            *(float4*)&xs[r][kq] = *(const float4*)&x[(size_t)(n0 + r)*HH + kk + kq];
        }
        #pragma unroll
        for (int l = 0; l < 3; l++) {
            int slot = tid + l*256;
            int k = slot / 24, c4 = (slot % 24) * 4;
            *(float4*)&ws[k][c4] = *(const float4*)&g_Wcat[(kk + k)*96 + c4];
        }
        __syncthreads();
        #pragma unroll
        for (int k = 0; k < 32; k++) {
            float qf[4], wf[6];
            #pragma unroll
            for (int i = 0; i < 4; i++) qf[i] = xs[tr*4 + i][k];
            #pragma unroll
            for (int j = 0; j < 6; j++) wf[j] = ws[k][tc*6 + j];
            #pragma unroll
            for (int i = 0; i < 4; i++)
                #pragma unroll
                for (int j = 0; j < 6; j++)
                    acc[i][j] = fmaf(qf[i], wf[j], acc[i][j]);
        }
        __syncthreads();
    }
    #pragma unroll
    for (int i = 0; i < 4; i++) {
        int n = n0 + tr*4 + i;
        #pragma unroll
        for (int j = 0; j < 6; j++) {
            int c = tc*6 + j;
            float* dst = (c < 32) ? g_qr : (c < 64) ? g_kr : g_v;
            dst[n*32 + (c & 31)] = acc[i][j];
        }
    }
}

// ---------------- kernel 2: fused attention ----------------
// Per block: one batch, 32 queries. Loop over 64-key tiles:
// scores (32x64x32 dot) -> exp -> write unnormalized probs + smem -> PV accumulate + rowsum.
__global__ __launch_bounds__(256) void attn_kernel(float* __restrict__ out,
                                                   float* __restrict__ probs) {
    __shared__ float qst[32][36];  // [feature][query], padded
    __shared__ float kst[32][66];  // [feature][key], padded
    __shared__ float vs[64][32];   // [key][d]
    __shared__ float es[32][66];   // [query][key], padded

    int tid = threadIdx.x;
    int b = blockIdx.y;
    int q0 = blockIdx.x * 32;
    size_t rowbase = (size_t)b * SS + q0;

    for (int idx = tid; idx < 32*32; idx += 256) {
        int r = idx >> 5, k = idx & 31;
        qst[k][r] = g_qr[(rowbase + r)*32 + k];
    }

    int qg = tid >> 5, tg = tid & 31;  // score phase: 4 queries x 2 keys per thread
    int pq = tid >> 3, dg = tid & 7;   // PV phase: 1 query x 4 dims per thread

    float acc0 = 0.f, acc1 = 0.f, acc2 = 0.f, acc3 = 0.f, sum = 0.f;

    for (int t0 = 0; t0 < SS; t0 += 64) {
        for (int idx = tid; idx < 64*32; idx += 256) {
            int r = idx >> 5, k = idx & 31;
            kst[k][r] = g_kr[((size_t)b*SS + t0 + r)*32 + k];
        }
        #pragma unroll
        for (int l = 0; l < 2; l++) {
            int slot = tid*2 + l;
            int r = slot >> 3, d4 = (slot & 7) << 2;
            *(float4*)&vs[r][d4] = *(const float4*)&g_v[((size_t)b*SS + t0 + r)*32 + d4];
        }
        __syncthreads();

        float sc[4][2] = {{0.f,0.f},{0.f,0.f},{0.f,0.f},{0.f,0.f}};
        #pragma unroll
        for (int k = 0; k < 32; k++) {
            float4 qf = *(const float4*)&qst[k][qg*4];     // broadcast within warp
            float2 kf = *(const float2*)&kst[k][tg*2];
            sc[0][0] = fmaf(qf.x, kf.x, sc[0][0]); sc[0][1] = fmaf(qf.x, kf.y, sc[0][1]);
            sc[1][0] = fmaf(qf.y, kf.x, sc[1][0]); sc[1][1] = fmaf(qf.y, kf.y, sc[1][1]);
            sc[2][0] = fmaf(qf.z, kf.x, sc[2][0]); sc[2][1] = fmaf(qf.z, kf.y, sc[2][1]);
            sc[3][0] = fmaf(qf.w, kf.x, sc[3][0]); sc[3][1] = fmaf(qf.w, kf.y, sc[3][1]);
        }
        #pragma unroll
        for (int i = 0; i < 4; i++) {
            float e0 = fexp(sc[i][0]);
            float e1 = fexp(sc[i][1]);
            int q = qg*4 + i, t = tg*2;
            *(float2*)&es[q][t] = make_float2(e0, e1);
            if (probs)
                *(float2*)&probs[(rowbase + q)*(size_t)SS + t0 + t] = make_float2(e0, e1);
        }
        __syncthreads();

        #pragma unroll 4
        for (int t = 0; t < 64; t++) {
            float e = es[pq][t];
            float4 vv = *(const float4*)&vs[t][dg*4];
            acc0 = fmaf(e, vv.x, acc0);
            acc1 = fmaf(e, vv.y, acc1);
            acc2 = fmaf(e, vv.z, acc2);
            acc3 = fmaf(e, vv.w, acc3);
            sum += e;
        }
        __syncthreads();
    }

    float inv = 1.0f / sum;
    size_t on = (rowbase + pq)*32 + dg*4;
    *(float4*)&out[on] = make_float4(acc0*inv, acc1*inv, acc2*inv, acc3*inv);
    if (dg == 0) g_invsum[rowbase + pq] = inv;
}

// ---------------- kernel 3: normalize probs ----------------
__global__ __launch_bounds__(256) void norm_kernel(float* __restrict__ probs) {
    size_t i = (size_t)blockIdx.x * blockDim.x + threadIdx.x;  // float4 index
    size_t row = i >> 9;                                       // / (S/4 = 512)
    float inv = g_invsum[row];
    float4 p = *(const float4*)&probs[i*4];
    p.x *= inv; p.y *= inv; p.z *= inv; p.w *= inv;
    *(float4*)&probs[i*4] = p;
}

// ---------------- launch ----------------
extern "C" void kernel_launch(void* const* d_in, const int* in_sizes, int n_in,
                              void* d_out, int out_size) {
    const float* x  = (const float*)d_in[0];
    const float* Wq = (const float*)d_in[1];
    const float* bq = (const float*)d_in[2];
    const float* Wk = (const float*)d_in[3];
    const float* bk = (const float*)d_in[4];
    const float* Wv = (const float*)d_in[5];
    const float* bv = (const float*)d_in[6];
    const float* RF = (const float*)d_in[7];

    float* outp = (float*)d_out;
    float* probs = nullptr;
    long long need = (long long)BB*SS*DD + (long long)BB*SS*SS;
    if ((long long)out_size >= need)
        probs = outp + (size_t)BB*SS*DD;

    prep_kernel<<<(HH*96 + 96 + 255)/256, 256>>>(Wq, bq, Wk, bk, Wv, bv, RF);
    proj_kernel<<<NP/64, 256>>>(x);
    dim3 g2(SS/32, BB);
    attn_kernel<<<g2, 256>>>(outp, probs);
    if (probs) {
        size_t n4 = (size_t)BB*SS*SS/4;
        norm_kernel<<<(unsigned)(n4/256), 256>>>(probs);
    }
}

// round 2
// speedup vs baseline: 1.0476x; 1.0476x over previous
#include <cuda_runtime.h>

#define BB 8
#define SS 2048
#define HH 768
#define DD 32
#define NP (BB*SS)   // 16384 total rows

// ---------------- scratch (no cudaMalloc allowed) ----------------
__device__ float g_Wcat[HH*96];   // [h][0:32)=Wqr*invsqrtD, [32:64)=Wkr, [64:96)=Wv^T
__device__ float g_bcat[96];
__device__ float g_qr[NP*DD];
__device__ float g_kr[NP*DD];
__device__ float g_v [NP*DD];
__device__ float g_invsum[NP];

// ---------------- fast exp on the FMA pipe (avoid MUFU bottleneck) ----------------
__device__ __forceinline__ float fexp(float x) {
    float y = x * 1.4426950408889634f;   // x * log2(e)
    float n = rintf(y);
    float f = y - n;                     // f in [-0.5, 0.5]
    // 2^f Taylor, degree 5: abs err ~2.4e-6
    float p = 1.3333558146e-3f;
    p = fmaf(p, f, 9.6181291976e-3f);
    p = fmaf(p, f, 5.5504108664e-2f);
    p = fmaf(p, f, 2.4022650695910071e-1f);
    p = fmaf(p, f, 6.9314718055994531e-1f);
    p = fmaf(p, f, 1.0f);
    int ni = (int)n;
    return __int_as_float(__float_as_int(p) + (ni << 23));
}

// ---------------- kernel 0: fold RF (and 1/sqrt(D)) into projection weights ----------------
__global__ void prep_kernel(const float* __restrict__ Wq, const float* __restrict__ bq,
                            const float* __restrict__ Wk, const float* __restrict__ bk,
                            const float* __restrict__ Wv, const float* __restrict__ bv,
                            const float* __restrict__ RF) {
    int idx = blockIdx.x * blockDim.x + threadIdx.x;
    const float invsD = 0.17677669529663687f;  // 1/sqrt(32)
    if (idx < HH*96) {
        int h = idx / 96, j = idx % 96;
        float r;
        if (j < 64) {
            const float* W = (j < 32) ? Wq : Wk;
            int f = j & 31;
            float acc = 0.f;
            #pragma unroll
            for (int d = 0; d < 32; d++) acc = fmaf(W[d*HH + h], RF[d*32 + f], acc);
            r = (j < 32) ? acc * invsD : acc;
        } else {
            r = Wv[(j - 64)*HH + h];
        }
        g_Wcat[h*96 + j] = r;
    } else if (idx < HH*96 + 96) {
        int j = idx - HH*96;
        float r;
        if (j < 64) {
            const float* bb = (j < 32) ? bq : bk;
            int f = j & 31;
            float acc = 0.f;
            #pragma unroll
            for (int d = 0; d < 32; d++) acc = fmaf(bb[d], RF[d*32 + f], acc);
            r = (j < 32) ? acc * invsD : acc;
        } else {
            r = bv[j - 64];
        }
        g_bcat[j] = r;
    }
}

// ---------------- kernel 1: fused projection GEMM  [16384,768] @ [768,96] ----------------
__global__ __launch_bounds__(256) void proj_kernel(const float* __restrict__ x) {
    __shared__ float xs[64][32];
    __shared__ float ws[32][96];
    __shared__ float bs[96];
    int tid = threadIdx.x;
    int n0 = blockIdx.x * 64;
    if (tid < 96) bs[tid] = g_bcat[tid];
    int tr = tid >> 4, tc = tid & 15;   // 16x16 threads; each does 4 rows x 6 cols
    __syncthreads();

    float acc[4][6];
    #pragma unroll
    for (int i = 0; i < 4; i++)
        #pragma unroll
        for (int j = 0; j < 6; j++) acc[i][j] = bs[tc*6 + j];

    for (int kk = 0; kk < HH; kk += 32) {
        #pragma unroll
        for (int l = 0; l < 2; l++) {
            int slot = tid*2 + l;
            int r = slot >> 3, kq = (slot & 7) << 2;
            *(float4*)&xs[r][kq] = *(const float4*)&x[(size_t)(n0 + r)*HH + kk + kq];
        }
        #pragma unroll
        for (int l = 0; l < 3; l++) {
            int slot = tid + l*256;
            int k = slot / 24, c4 = (slot % 24) * 4;
            *(float4*)&ws[k][c4] = *(const float4*)&g_Wcat[(kk + k)*96 + c4];
        }
        __syncthreads();
        #pragma unroll
        for (int k = 0; k < 32; k++) {
            float qf[4], wf[6];
            #pragma unroll
            for (int i = 0; i < 4; i++) qf[i] = xs[tr*4 + i][k];
            #pragma unroll
            for (int j = 0; j < 6; j++) wf[j] = ws[k][tc*6 + j];
            #pragma unroll
            for (int i = 0; i < 4; i++)
                #pragma unroll
                for (int j = 0; j < 6; j++)
                    acc[i][j] = fmaf(qf[i], wf[j], acc[i][j]);
        }
        __syncthreads();
    }
    #pragma unroll
    for (int i = 0; i < 4; i++) {
        int n = n0 + tr*4 + i;
        #pragma unroll
        for (int j = 0; j < 6; j++) {
            int c = tc*6 + j;
            float* dst = (c < 32) ? g_qr : (c < 64) ? g_kr : g_v;
            dst[n*32 + (c & 31)] = acc[i][j];
        }
    }
}

// ---------------- kernel 2: fused attention ----------------
// Per block: one batch, 32 queries. Loop over 64-key tiles:
// scores (32x64x32 dot) -> exp -> write unnormalized probs + smem -> PV accumulate + rowsum.
__global__ __launch_bounds__(256) void attn_kernel(float* __restrict__ out,
                                                   float* __restrict__ probs) {
    __shared__ float qst[32][36];  // [feature][query], padded
    __shared__ float kst[32][66];  // [feature][key], padded
    __shared__ float vs[64][32];   // [key][d]
    __shared__ float es[32][66];   // [query][key], padded

    int tid = threadIdx.x;
    int b = blockIdx.y;
    int q0 = blockIdx.x * 32;
    size_t rowbase = (size_t)b * SS + q0;

    for (int idx = tid; idx < 32*32; idx += 256) {
        int r = idx >> 5, k = idx & 31;
        qst[k][r] = g_qr[(rowbase + r)*32 + k];
    }

    int qg = tid >> 5, tg = tid & 31;  // score phase: 4 queries x 2 keys per thread
    int pq = tid >> 3, dg = tid & 7;   // PV phase: 1 query x 4 dims per thread

    float acc0 = 0.f, acc1 = 0.f, acc2 = 0.f, acc3 = 0.f, sum = 0.f;

    for (int t0 = 0; t0 < SS; t0 += 64) {
        for (int idx = tid; idx < 64*32; idx += 256) {
            int r = idx >> 5, k = idx & 31;
            kst[k][r] = g_kr[((size_t)b*SS + t0 + r)*32 + k];
        }
        #pragma unroll
        for (int l = 0; l < 2; l++) {
            int slot = tid*2 + l;
            int r = slot >> 3, d4 = (slot & 7) << 2;
            *(float4*)&vs[r][d4] = *(const float4*)&g_v[((size_t)b*SS + t0 + r)*32 + d4];
        }
        __syncthreads();

        float sc[4][2] = {{0.f,0.f},{0.f,0.f},{0.f,0.f},{0.f,0.f}};
        #pragma unroll
        for (int k = 0; k < 32; k++) {
            float4 qf = *(const float4*)&qst[k][qg*4];     // broadcast within warp
            float2 kf = *(const float2*)&kst[k][tg*2];
            sc[0][0] = fmaf(qf.x, kf.x, sc[0][0]); sc[0][1] = fmaf(qf.x, kf.y, sc[0][1]);
            sc[1][0] = fmaf(qf.y, kf.x, sc[1][0]); sc[1][1] = fmaf(qf.y, kf.y, sc[1][1]);
            sc[2][0] = fmaf(qf.z, kf.x, sc[2][0]); sc[2][1] = fmaf(qf.z, kf.y, sc[2][1]);
            sc[3][0] = fmaf(qf.w, kf.x, sc[3][0]); sc[3][1] = fmaf(qf.w, kf.y, sc[3][1]);
        }
        #pragma unroll
        for (int i = 0; i < 4; i++) {
            float e0 = fexp(sc[i][0]);
            float e1 = fexp(sc[i][1]);
            int q = qg*4 + i, t = tg*2;
            *(float2*)&es[q][t] = make_float2(e0, e1);
            if (probs)
                *(float2*)&probs[(rowbase + q)*(size_t)SS + t0 + t] = make_float2(e0, e1);
        }
        __syncthreads();

        #pragma unroll 4
        for (int t = 0; t < 64; t++) {
            float e = es[pq][t];
            float4 vv = *(const float4*)&vs[t][dg*4];
            acc0 = fmaf(e, vv.x, acc0);
            acc1 = fmaf(e, vv.y, acc1);
            acc2 = fmaf(e, vv.z, acc2);
            acc3 = fmaf(e, vv.w, acc3);
            sum += e;
        }
        __syncthreads();
    }

    float inv = 1.0f / sum;
    size_t on = (rowbase + pq)*32 + dg*4;
    *(float4*)&out[on] = make_float4(acc0*inv, acc1*inv, acc2*inv, acc3*inv);
    if (dg == 0) g_invsum[rowbase + pq] = inv;
}

// ---------------- kernel 3: normalize probs ----------------
__global__ __launch_bounds__(256) void norm_kernel(float* __restrict__ probs) {
    size_t i = (size_t)blockIdx.x * blockDim.x + threadIdx.x;  // float4 index
    size_t row = i >> 9;                                       // / (S/4 = 512)
    float inv = g_invsum[row];
    float4 p = *(const float4*)&probs[i*4];
    p.x *= inv; p.y *= inv; p.z *= inv; p.w *= inv;
    *(float4*)&probs[i*4] = p;
}

// ---------------- launch ----------------
extern "C" void kernel_launch(void* const* d_in, const int* in_sizes, int n_in,
                              void* d_out, int out_size) {
    const float* x  = (const float*)d_in[0];
    const float* Wq = (const float*)d_in[1];
    const float* bq = (const float*)d_in[2];
    const float* Wk = (const float*)d_in[3];
    const float* bk = (const float*)d_in[4];
    const float* Wv = (const float*)d_in[5];
    const float* bv = (const float*)d_in[6];
    const float* RF = (const float*)d_in[7];

    float* outp = (float*)d_out;
    float* probs = nullptr;
    long long need = (long long)BB*SS*DD + (long long)BB*SS*SS;
    if ((long long)out_size >= need)
        probs = outp + (size_t)BB*SS*DD;

    prep_kernel<<<(HH*96 + 96 + 255)/256, 256>>>(Wq, bq, Wk, bk, Wv, bv, RF);
    proj_kernel<<<NP/64, 256>>>(x);
    dim3 g2(SS/32, BB);
    attn_kernel<<<g2, 256>>>(outp, probs);
    if (probs) {
        size_t n4 = (size_t)BB*SS*SS/4;
        norm_kernel<<<(unsigned)(n4/256), 256>>>(probs);
    }
}

// round 3
// speedup vs baseline: 1.0479x; 1.0003x over previous
#include <cuda_runtime.h>

#define BB 8
#define SS 2048
#define HH 768
#define DD 32
#define NP (BB*SS)   // 16384 total rows

// ---------------- scratch (no cudaMalloc allowed) ----------------
__device__ float g_Wcat[HH*96];   // [h][0:32)=Wqr*invsqrtD, [32:64)=Wkr, [64:96)=Wv^T
__device__ float g_bcat[96];
__device__ float g_qr[NP*DD];
__device__ float g_kr[NP*DD];
__device__ float g_v [NP*DD];
__device__ float g_invsum[NP];

// ---------------- fast exp on the FMA pipe (avoid MUFU bottleneck) ----------------
__device__ __forceinline__ float fexp(float x) {
    float y = x * 1.4426950408889634f;   // x * log2(e)
    float n = rintf(y);
    float f = y - n;                     // f in [-0.5, 0.5]
    // 2^f Taylor, degree 5: abs err ~2.4e-6
    float p = 1.3333558146e-3f;
    p = fmaf(p, f, 9.6181291976e-3f);
    p = fmaf(p, f, 5.5504108664e-2f);
    p = fmaf(p, f, 2.4022650695910071e-1f);
    p = fmaf(p, f, 6.9314718055994531e-1f);
    p = fmaf(p, f, 1.0f);
    int ni = (int)n;
    return __int_as_float(__float_as_int(p) + (ni << 23));
}

// ---------------- kernel 0: fold RF (and 1/sqrt(D)) into projection weights ----------------
__global__ void prep_kernel(const float* __restrict__ Wq, const float* __restrict__ bq,
                            const float* __restrict__ Wk, const float* __restrict__ bk,
                            const float* __restrict__ Wv, const float* __restrict__ bv,
                            const float* __restrict__ RF) {
    int idx = blockIdx.x * blockDim.x + threadIdx.x;
    const float invsD = 0.17677669529663687f;  // 1/sqrt(32)
    if (idx < HH*96) {
        int h = idx / 96, j = idx % 96;
        float r;
        if (j < 64) {
            const float* W = (j < 32) ? Wq : Wk;
            int f = j & 31;
            float acc = 0.f;
            #pragma unroll
            for (int d = 0; d < 32; d++) acc = fmaf(W[d*HH + h], RF[d*32 + f], acc);
            r = (j < 32) ? acc * invsD : acc;
        } else {
            r = Wv[(j - 64)*HH + h];
        }
        g_Wcat[h*96 + j] = r;
    } else if (idx < HH*96 + 96) {
        int j = idx - HH*96;
        float r;
        if (j < 64) {
            const float* bb = (j < 32) ? bq : bk;
            int f = j & 31;
            float acc = 0.f;
            #pragma unroll
            for (int d = 0; d < 32; d++) acc = fmaf(bb[d], RF[d*32 + f], acc);
            r = (j < 32) ? acc * invsD : acc;
        } else {
            r = bv[j - 64];
        }
        g_bcat[j] = r;
    }
}

// ---------------- kernel 1: fused projection GEMM  [16384,768] @ [768,96] ----------------
__global__ __launch_bounds__(256) void proj_kernel(const float* __restrict__ x) {
    __shared__ float xs[64][32];
    __shared__ float ws[32][96];
    __shared__ float bs[96];
    int tid = threadIdx.x;
    int n0 = blockIdx.x * 64;
    if (tid < 96) bs[tid] = g_bcat[tid];
    int tr = tid >> 4, tc = tid & 15;   // 16x16 threads; each does 4 rows x 6 cols
    __syncthreads();

    float acc[4][6];
    #pragma unroll
    for (int i = 0; i < 4; i++)
        #pragma unroll
        for (int j = 0; j < 6; j++) acc[i][j] = bs[tc*6 + j];

    for (int kk = 0; kk < HH; kk += 32) {
        #pragma unroll
        for (int l = 0; l < 2; l++) {
            int slot = tid*2 + l;
            int r = slot >> 3, kq = (slot & 7) << 2;
            *(float4*)&xs[r][kq] = *(const float4*)&x[(size_t)(n0 + r)*HH + kk + kq];
        }
        #pragma unroll
        for (int l = 0; l < 3; l++) {
            int slot = tid + l*256;
            int k = slot / 24, c4 = (slot % 24) * 4;
            *(float4*)&ws[k][c4] = *(const float4*)&g_Wcat[(kk + k)*96 + c4];
        }
        __syncthreads();
        #pragma unroll
        for (int k = 0; k < 32; k++) {
            float qf[4], wf[6];
            #pragma unroll
            for (int i = 0; i < 4; i++) qf[i] = xs[tr*4 + i][k];
            #pragma unroll
            for (int j = 0; j < 6; j++) wf[j] = ws[k][tc*6 + j];
            #pragma unroll
            for (int i = 0; i < 4; i++)
                #pragma unroll
                for (int j = 0; j < 6; j++)
                    acc[i][j] = fmaf(qf[i], wf[j], acc[i][j]);
        }
        __syncthreads();
    }
    #pragma unroll
    for (int i = 0; i < 4; i++) {
        int n = n0 + tr*4 + i;
        #pragma unroll
        for (int j = 0; j < 6; j++) {
            int c = tc*6 + j;
            float* dst = (c < 32) ? g_qr : (c < 64) ? g_kr : g_v;
            dst[n*32 + (c & 31)] = acc[i][j];
        }
    }
}

// ---------------- kernel 2: fused attention ----------------
// Per block: one batch, 32 queries. Loop over 64-key tiles:
// scores (32x64x32 dot) -> exp -> write unnormalized probs + smem -> PV accumulate + rowsum.
__global__ __launch_bounds__(256) void attn_kernel(float* __restrict__ out,
                                                   float* __restrict__ probs) {
    __shared__ float qst[32][36];  // [feature][query], padded
    __shared__ float kst[32][66];  // [feature][key], padded
    __shared__ float vs[64][32];   // [key][d]
    __shared__ float es[32][66];   // [query][key], padded

    int tid = threadIdx.x;
    int b = blockIdx.y;
    int q0 = blockIdx.x * 32;
    size_t rowbase = (size_t)b * SS + q0;

    for (int idx = tid; idx < 32*32; idx += 256) {
        int r = idx >> 5, k = idx & 31;
        qst[k][r] = g_qr[(rowbase + r)*32 + k];
    }

    int qg = tid >> 5, tg = tid & 31;  // score phase: 4 queries x 2 keys per thread
    int pq = tid >> 3, dg = tid & 7;   // PV phase: 1 query x 4 dims per thread

    float acc0 = 0.f, acc1 = 0.f, acc2 = 0.f, acc3 = 0.f, sum = 0.f;

    for (int t0 = 0; t0 < SS; t0 += 64) {
        for (int idx = tid; idx < 64*32; idx += 256) {
            int r = idx >> 5, k = idx & 31;
            kst[k][r] = g_kr[((size_t)b*SS + t0 + r)*32 + k];
        }
        #pragma unroll
        for (int l = 0; l < 2; l++) {
            int slot = tid*2 + l;
            int r = slot >> 3, d4 = (slot & 7) << 2;
            *(float4*)&vs[r][d4] = *(const float4*)&g_v[((size_t)b*SS + t0 + r)*32 + d4];
        }
        __syncthreads();

        float sc[4][2] = {{0.f,0.f},{0.f,0.f},{0.f,0.f},{0.f,0.f}};
        #pragma unroll
        for (int k = 0; k < 32; k++) {
            float4 qf = *(const float4*)&qst[k][qg*4];     // broadcast within warp
            float2 kf = *(const float2*)&kst[k][tg*2];
            sc[0][0] = fmaf(qf.x, kf.x, sc[0][0]); sc[0][1] = fmaf(qf.x, kf.y, sc[0][1]);
            sc[1][0] = fmaf(qf.y, kf.x, sc[1][0]); sc[1][1] = fmaf(qf.y, kf.y, sc[1][1]);
            sc[2][0] = fmaf(qf.z, kf.x, sc[2][0]); sc[2][1] = fmaf(qf.z, kf.y, sc[2][1]);
            sc[3][0] = fmaf(qf.w, kf.x, sc[3][0]); sc[3][1] = fmaf(qf.w, kf.y, sc[3][1]);
        }
        #pragma unroll
        for (int i = 0; i < 4; i++) {
            float e0 = fexp(sc[i][0]);
            float e1 = fexp(sc[i][1]);
            int q = qg*4 + i, t = tg*2;
            *(float2*)&es[q][t] = make_float2(e0, e1);
            if (probs)
                *(float2*)&probs[(rowbase + q)*(size_t)SS + t0 + t] = make_float2(e0, e1);
        }
        __syncthreads();

        #pragma unroll 4
        for (int t = 0; t < 64; t++) {
            float e = es[pq][t];
            float4 vv = *(const float4*)&vs[t][dg*4];
            acc0 = fmaf(e, vv.x, acc0);
            acc1 = fmaf(e, vv.y, acc1);
            acc2 = fmaf(e, vv.z, acc2);
            acc3 = fmaf(e, vv.w, acc3);
            sum += e;
        }
        __syncthreads();
    }

    float inv = 1.0f / sum;
    size_t on = (rowbase + pq)*32 + dg*4;
    *(float4*)&out[on] = make_float4(acc0*inv, acc1*inv, acc2*inv, acc3*inv);
    if (dg == 0) g_invsum[rowbase + pq] = inv;
}

// ---------------- kernel 3: normalize probs ----------------
__global__ __launch_bounds__(256) void norm_kernel(float* __restrict__ probs) {
    size_t i = (size_t)blockIdx.x * blockDim.x + threadIdx.x;  // float4 index
    size_t row = i >> 9;                                       // / (S/4 = 512)
    float inv = g_invsum[row];
    float4 p = *(const float4*)&probs[i*4];
    p.x *= inv; p.y *= inv; p.z *= inv; p.w *= inv;
    *(float4*)&probs[i*4] = p;
}

// ---------------- launch ----------------
extern "C" void kernel_launch(void* const* d_in, const int* in_sizes, int n_in,
                              void* d_out, int out_size) {
    const float* x  = (const float*)d_in[0];
    const float* Wq = (const float*)d_in[1];
    const float* bq = (const float*)d_in[2];
    const float* Wk = (const float*)d_in[3];
    const float* bk = (const float*)d_in[4];
    const float* Wv = (const float*)d_in[5];
    const float* bv = (const float*)d_in[6];
    const float* RF = (const float*)d_in[7];

    float* outp = (float*)d_out;
    float* probs = nullptr;
    long long need = (long long)BB*SS*DD + (long long)BB*SS*SS;
    if ((long long)out_size >= need)
        probs = outp + (size_t)BB*SS*DD;

    prep_kernel<<<(HH*96 + 96 + 255)/256, 256>>>(Wq, bq, Wk, bk, Wv, bv, RF);
    proj_kernel<<<NP/64, 256>>>(x);
    dim3 g2(SS/32, BB);
    attn_kernel<<<g2, 256>>>(outp, probs);
    if (probs) {
        size_t n4 = (size_t)BB*SS*SS/4;
        norm_kernel<<<(unsigned)(n4/256), 256>>>(probs);
    }
}